// round 16
// baseline (speedup 1.0000x reference)
#include <cuda_runtime.h>
#include <cuda_bf16.h>

typedef unsigned long long u64t;

// ---------- scratch ----------
__device__ float g_part[128];
__device__ float g_mvec[64];
__device__ int   g_ctr;
__device__ __align__(16) __nv_bfloat16 g_Qb[4 * 4096 * 64]; // [w][n][d] normalized Q (=K)
__device__ __align__(16) __nv_bfloat16 g_Vb[4 * 4096 * 64]; // [w][n][c]
__device__ float g_attn[1048576];                           // raw reshape (64,128,128)
__device__ float g_t [1048576];
__device__ float g_z1[1048576];
__device__ float g_wc1[36864];   // tf32 weights, [co][ci*9+tap]
__device__ float g_wc2[36864];
__device__ float g_w3c[64 * 64]; // tf32, [co][ci]
__device__ float g_wlT[65 * 64];

// ---------- helpers ----------
__device__ __forceinline__ u64t pk2(float a, float b) {
    u64t r; asm("mov.b64 %0,{%1,%2};" : "=l"(r) : "f"(a), "f"(b)); return r;
}
__device__ __forceinline__ void upk2(u64t v, float& a, float& b) {
    asm("mov.b64 {%0,%1},%2;" : "=f"(a), "=f"(b) : "l"(v));
}
__device__ __forceinline__ u64t fma2(u64t a, u64t b, u64t c) {
    u64t d; asm("fma.rn.f32x2 %0,%1,%2,%3;" : "=l"(d) : "l"(a), "l"(b), "l"(c)); return d;
}
__device__ __forceinline__ u64t add2(u64t a, u64t b) {
    u64t d; asm("add.rn.f32x2 %0,%1,%2;" : "=l"(d) : "l"(a), "l"(b)); return d;
}
__device__ __forceinline__ unsigned cvt_tf32(float f) {
    unsigned u; asm("cvt.rna.tf32.f32 %0,%1;" : "=r"(u) : "f"(f)); return u;
}
__device__ __forceinline__ unsigned packbf(float lo, float hi) {
    __nv_bfloat162 h = __floats2bfloat162_rn(lo, hi);
    return *(unsigned*)&h;
}
__device__ __forceinline__ void cp16(unsigned dst, const void* src) {
    asm volatile("cp.async.cg.shared.global [%0], [%1], 16;" :: "r"(dst), "l"(src));
}

// ---------- merged: mean stage1 + weight prep + mean stage2 ----------
__global__ void prep_all(const float* __restrict__ x,  const float* __restrict__ w1,
                         const float* __restrict__ w2, const float* __restrict__ w3,
                         const float* __restrict__ wl, const float* __restrict__ wqk) {
    int t = threadIdx.x, bid = blockIdx.x;       // 144 blocks x 256
    if (bid < 128) {
        __shared__ float red[256];
        int base = bid * 8192;
        float s = 0.f;
#pragma unroll
        for (int k = 0; k < 32; k++) s += x[base + k * 256 + t];
        red[t] = s; __syncthreads();
        for (int o = 128; o; o >>= 1) { if (t < o) red[t] += red[t + o]; __syncthreads(); }
        if (t == 0) g_part[bid] = red[0];
    }
    int i = bid * 256 + t;
    g_wc1[i] = __uint_as_float(cvt_tf32(w1[i]));
    g_wc2[i] = __uint_as_float(cvt_tf32(w2[i]));
    if (i < 4096) g_w3c[i] = __uint_as_float(cvt_tf32(w3[i]));
    if (i < 4160) { int co = i / 65, ci = i - co * 65; g_wlT[ci * 64 + co] = wl[i]; }
    __syncthreads();
    __shared__ int lastf;
    if (t == 0) {
        __threadfence();
        lastf = (atomicAdd(&g_ctr, 1) == 143);
    }
    __syncthreads();
    if (lastf) {
        __threadfence();
        __shared__ float red2[128];
        __shared__ float m_sh;
        if (t < 128) red2[t] = g_part[t];
        __syncthreads();
        for (int o = 64; o; o >>= 1) { if (t < 128 && t < o) red2[t] += red2[t + o]; __syncthreads(); }
        if (t == 0) { m_sh = red2[0] * (1.0f / 1048576.0f); g_ctr = 0; }
        __syncthreads();
        if (t < 64) {
            float cs = 0.f;
            for (int c = 0; c < 64; c++) cs += wqk[c * 64 + t];
            g_mvec[t] = m_sh * cs;
        }
    }
}

// ---------- build normalized Q (bf16) and V (bf16); 16 rows/block ----------
__global__ void __launch_bounds__(256) qv_build(const float* __restrict__ x,
                                                const float* __restrict__ wqk) {
    __shared__ float wT[64 * 66];   // [e][c] pitch 66
    __shared__ float xs[16 * 66];   // [j][c] pitch 66
    int b = blockIdx.x;             // 1024 blocks
    int w = b >> 8, rb = b & 255;
    int hs = rb >> 2, ws0 = (rb & 3) * 16;
    int dh = w >> 1, dw = w & 1;
    int t = threadIdx.x;
    int h = 2 * hs + dh;
    for (int i = t; i < 4096; i += 256)
        wT[(i & 63) * 66 + (i >> 6)] = wqk[i];
#pragma unroll
    for (int pass = 0; pass < 4; pass++) {
        int i = pass * 256 + t;
        int j = i & 15, c = i >> 4;
        xs[j * 66 + c] = x[c * 16384 + h * 128 + 2 * (ws0 + j) + dw];
    }
    __syncthreads();
    int nbase = hs * 64 + ws0;
#pragma unroll
    for (int pass = 0; pass < 4; pass++) {       // V bf16
        int i = pass * 256 + t;
        int c = i & 63, j = i >> 6;
        g_Vb[(size_t)(w * 4096 + nbase + j) * 64 + c] = __float2bfloat16(xs[j * 66 + c]);
    }
    int lane = t & 31, warp = t >> 5;
    int j0 = warp * 2, j1 = j0 + 1;
    float mv0 = g_mvec[lane], mv1 = g_mvec[lane + 32];
    float u00 = 0.f, u01 = 0.f, u10 = 0.f, u11 = 0.f;
    const float2* w0p = (const float2*)(wT + lane * 66);
    const float2* w1p = (const float2*)(wT + (lane + 32) * 66);
    const float2* x0p = (const float2*)(xs + j0 * 66);
    const float2* x1p = (const float2*)(xs + j1 * 66);
#pragma unroll 8
    for (int cc = 0; cc < 32; cc++) {
        float2 wv0 = w0p[cc], wv1 = w1p[cc];
        float2 xv0 = x0p[cc], xv1 = x1p[cc];
        u00 = fmaf(wv0.x, xv0.x, u00); u00 = fmaf(wv0.y, xv0.y, u00);
        u01 = fmaf(wv1.x, xv0.x, u01); u01 = fmaf(wv1.y, xv0.y, u01);
        u10 = fmaf(wv0.x, xv1.x, u10); u10 = fmaf(wv0.y, xv1.y, u10);
        u11 = fmaf(wv1.x, xv1.x, u11); u11 = fmaf(wv1.y, xv1.y, u11);
    }
    u00 -= mv0; u01 -= mv1; u10 -= mv0; u11 -= mv1;
    float ss0 = u00 * u00 + u01 * u01;
    float ss1 = u10 * u10 + u11 * u11;
#pragma unroll
    for (int o = 16; o; o >>= 1) {
        ss0 += __shfl_xor_sync(0xFFFFFFFFu, ss0, o);
        ss1 += __shfl_xor_sync(0xFFFFFFFFu, ss1, o);
    }
    float r0 = rsqrtf(ss0 + 1e-24f), r1 = rsqrtf(ss1 + 1e-24f);
    __nv_bfloat16* q0p = g_Qb + (size_t)(w * 4096 + nbase + j0) * 64;
    __nv_bfloat16* q1p = g_Qb + (size_t)(w * 4096 + nbase + j1) * 64;
    q0p[lane] = __float2bfloat16(u00 * r0);
    q0p[lane + 32] = __float2bfloat16(u01 * r0);
    q1p[lane] = __float2bfloat16(u10 * r1);
    q1p[lane + 32] = __float2bfloat16(u11 * r1);
}

// ---------- mma helpers ----------
__device__ __forceinline__ void ldsm4(unsigned addr, unsigned& r0, unsigned& r1,
                                      unsigned& r2, unsigned& r3) {
    asm volatile("ldmatrix.sync.aligned.m8n8.x4.shared.b16 {%0,%1,%2,%3}, [%4];"
                 : "=r"(r0), "=r"(r1), "=r"(r2), "=r"(r3) : "r"(addr));
}
__device__ __forceinline__ void ldsm4t(unsigned addr, unsigned& r0, unsigned& r1,
                                       unsigned& r2, unsigned& r3) {
    asm volatile("ldmatrix.sync.aligned.m8n8.x4.trans.shared.b16 {%0,%1,%2,%3}, [%4];"
                 : "=r"(r0), "=r"(r1), "=r"(r2), "=r"(r3) : "r"(addr));
}
__device__ __forceinline__ void mma16816(float* c, const unsigned* a, unsigned b0, unsigned b1) {
    asm volatile("mma.sync.aligned.m16n8k16.row.col.f32.bf16.bf16.f32 "
                 "{%0,%1,%2,%3},{%4,%5,%6,%7},{%8,%9},{%0,%1,%2,%3};"
                 : "+f"(c[0]), "+f"(c[1]), "+f"(c[2]), "+f"(c[3])
                 : "r"(a[0]), "r"(a[1]), "r"(a[2]), "r"(a[3]), "r"(b0), "r"(b1));
}
__device__ __forceinline__ void mma_tf32(float* c, unsigned a0, unsigned a1, unsigned a2,
                                         unsigned a3, unsigned b0, unsigned b1) {
    asm volatile("mma.sync.aligned.m16n8k8.row.col.f32.tf32.tf32.f32 "
                 "{%0,%1,%2,%3},{%4,%5,%6,%7},{%8,%9},{%0,%1,%2,%3};"
                 : "+f"(c[0]), "+f"(c[1]), "+f"(c[2]), "+f"(c[3])
                 : "r"(a0), "r"(a1), "r"(a2), "r"(a3), "r"(b0), "r"(b1));
}

// ---------- attention: bf16 HMMA, 64q CTA x 4 warps, ILP2, double-buffered ----------
#define PITCHB 144       // bytes per smem row (72 bf16)
#define BUFB   36864     // one buffer: K(18432) + V(18432)
__global__ void __launch_bounds__(128, 2) attn_mma() {
    extern __shared__ char smx[];
    unsigned smU = (unsigned)__cvta_generic_to_shared(smx);
    int w = blockIdx.y;
    int qb = blockIdx.x * 64;
    int t = threadIdx.x, warp = t >> 5, lane = t & 31;
    int g = lane >> 2, tig = lane & 3;
    const __nv_bfloat16* Qg = g_Qb + (size_t)w * 4096 * 64;
    const __nv_bfloat16* Vg = g_Vb + (size_t)w * 4096 * 64;

    int q0 = qb + warp * 16;
    unsigned qa[4][4];
#pragma unroll
    for (int s = 0; s < 4; s++) {
        const __nv_bfloat16* bp = Qg + (q0 + g) * 64 + s * 16 + 2 * tig;
        qa[s][0] = *(const unsigned*)(bp);
        qa[s][1] = *(const unsigned*)(bp + 8 * 64);
        qa[s][2] = *(const unsigned*)(bp + 8);
        qa[s][3] = *(const unsigned*)(bp + 8 * 64 + 8);
    }

    float o[8][4];
#pragma unroll
    for (int i = 0; i < 8; i++)
#pragma unroll
        for (int jx = 0; jx < 4; jx++) o[i][jx] = 0.f;
    u64t rsA = 0ull, rsB = 0ull;

    int mi = lane >> 3, li = lane & 7;
    unsigned kOff = ((mi >> 1) * 8 + li) * PITCHB + (mi & 1) * 16;
    unsigned vOff = ((mi & 1) * 8 + li) * PITCHB + (mi >> 1) * 16;

    const u64t C18 = pk2(0.125f, 0.125f);
    const u64t K3 = pk2(0.1889038f, 0.1889038f);
    const u64t K2 = pk2(0.4964532f, 0.4964532f);
    const u64t K1 = pk2(1.0001804f, 1.0001804f);
    const u64t K0 = pk2(0.9999986f, 0.9999986f);

#define ISSUE(ch) do {                                                        \
        int _b = (ch) & 1;                                                    \
        unsigned _kd = smU + _b * BUFB, _vd = _kd + 18432;                    \
        const char* _ks = (const char*)(Qg + (ch) * 128 * 64);                \
        const char* _vs = (const char*)(Vg + (ch) * 128 * 64);                \
        _Pragma("unroll")                                                     \
        for (int _i = 0; _i < 8; _i++) {                                      \
            int _idx = t + _i * 128;                                          \
            int _r = _idx >> 3, _cg = _idx & 7;                               \
            unsigned _o = _r * PITCHB + _cg * 16;                             \
            unsigned _go = _r * 128 + _cg * 16;                               \
            cp16(_kd + _o, _ks + _go);                                        \
            cp16(_vd + _o, _vs + _go);                                        \
        }                                                                     \
        asm volatile("cp.async.commit_group;");                               \
    } while (0)

#define SOFTEXP(p0, p1, ea) do {                                              \
        u64t d0 = pk2(p0[0], p0[1]), d1 = pk2(p0[2], p0[3]);                  \
        u64t d2 = pk2(p1[0], p1[1]), d3 = pk2(p1[2], p1[3]);                  \
        u64t s0 = fma2(d0, C18, C18), s1 = fma2(d1, C18, C18);                \
        u64t s2 = fma2(d2, C18, C18), s3 = fma2(d3, C18, C18);                \
        u64t e0 = fma2(s0, K3, K2); e0 = fma2(s0, e0, K1); e0 = fma2(s0, e0, K0); \
        u64t e1 = fma2(s1, K3, K2); e1 = fma2(s1, e1, K1); e1 = fma2(s1, e1, K0); \
        u64t e2 = fma2(s2, K3, K2); e2 = fma2(s2, e2, K1); e2 = fma2(s2, e2, K0); \
        u64t e3 = fma2(s3, K3, K2); e3 = fma2(s3, e3, K1); e3 = fma2(s3, e3, K0); \
        rsA = add2(rsA, e0); rsB = add2(rsB, e1);                             \
        rsA = add2(rsA, e2); rsB = add2(rsB, e3);                             \
        float f0, f1;                                                         \
        upk2(e0, f0, f1); ea[0] = packbf(f0, f1);                             \
        upk2(e1, f0, f1); ea[1] = packbf(f0, f1);                             \
        upk2(e2, f0, f1); ea[2] = packbf(f0, f1);                             \
        upk2(e3, f0, f1); ea[3] = packbf(f0, f1);                             \
    } while (0)

    ISSUE(0);
    ISSUE(1);

    for (int ch = 0; ch < 32; ch++) {
        if (ch < 31) asm volatile("cp.async.wait_group 1;");
        else         asm volatile("cp.async.wait_group 0;");
        __syncthreads();
        unsigned ksU = smU + (ch & 1) * BUFB;
        unsigned vsU = ksU + 18432;

#pragma unroll
        for (int jp = 0; jp < 8; jp += 2) {
            float pA0[4] = {0.f, 0.f, 0.f, 0.f}, pA1[4] = {0.f, 0.f, 0.f, 0.f};
            float pB0[4] = {0.f, 0.f, 0.f, 0.f}, pB1[4] = {0.f, 0.f, 0.f, 0.f};
#pragma unroll
            for (int s = 0; s < 4; s++) {
                unsigned r0, r1, r2, r3;
                ldsm4(ksU + jp * (16 * PITCHB) + s * 32 + kOff, r0, r1, r2, r3);
                mma16816(pA0, qa[s], r0, r1);
                mma16816(pA1, qa[s], r2, r3);
                ldsm4(ksU + (jp + 1) * (16 * PITCHB) + s * 32 + kOff, r0, r1, r2, r3);
                mma16816(pB0, qa[s], r0, r1);
                mma16816(pB1, qa[s], r2, r3);
            }
            unsigned eaA[4], eaB[4];
            SOFTEXP(pA0, pA1, eaA);
            SOFTEXP(pB0, pB1, eaB);
#pragma unroll
            for (int cp = 0; cp < 4; cp++) {
                unsigned r0, r1, r2, r3;
                ldsm4t(vsU + jp * (16 * PITCHB) + cp * 32 + vOff, r0, r1, r2, r3);
                mma16816(o[2 * cp],     eaA, r0, r1);
                mma16816(o[2 * cp + 1], eaA, r2, r3);
                ldsm4t(vsU + (jp + 1) * (16 * PITCHB) + cp * 32 + vOff, r0, r1, r2, r3);
                mma16816(o[2 * cp],     eaB, r0, r1);
                mma16816(o[2 * cp + 1], eaB, r2, r3);
            }
        }
        __syncthreads();
        if (ch + 2 < 32) ISSUE(ch + 2);
    }

    float rs0a, rs0b, rs1a, rs1b;
    upk2(rsA, rs0a, rs0b); upk2(rsB, rs1a, rs1b);
    float rs0 = rs0a + rs0b, rs1 = rs1a + rs1b;
    rs0 += __shfl_xor_sync(0xFFFFFFFFu, rs0, 1);
    rs0 += __shfl_xor_sync(0xFFFFFFFFu, rs0, 2);
    rs1 += __shfl_xor_sync(0xFFFFFFFFu, rs1, 1);
    rs1 += __shfl_xor_sync(0xFFFFFFFFu, rs1, 2);
    float i0 = 1.f / rs0, i1 = 1.f / rs1;

    float* outp = g_attn + (size_t)(w * 4096 + q0) * 64;
#pragma unroll
    for (int c = 0; c < 8; c++) {
        int col = c * 8 + 2 * tig;
        *(float2*)(outp + g * 64 + col)       = make_float2(o[c][0] * i0, o[c][1] * i0);
        *(float2*)(outp + (g + 8) * 64 + col) = make_float2(o[c][2] * i1, o[c][3] * i1);
    }
}

// ---------- fused 1x1 conv (attn 64ch + unet 1ch) + bias + residual -> g_t ----------
// 256 blocks x 256 threads: block = 64 pixels, thread = (2 pixels, 8-co group)
__global__ void __launch_bounds__(256) convl_fused(const float* __restrict__ unet,
                                                   const float* __restrict__ x,
                                                   const float* __restrict__ bias) {
    __shared__ float w_s[4160];
    int t = threadIdx.x;
    for (int i = t; i < 4160; i += 256) w_s[i] = g_wlT[i];
    __syncthreads();
    int p = (blockIdx.x * 32 + (t & 31)) * 2;
    int co0 = (t >> 5) * 8;
    float accA[8], accB[8];
#pragma unroll
    for (int i = 0; i < 8; i++) { accA[i] = 0.f; accB[i] = 0.f; }
#pragma unroll 8
    for (int ci = 0; ci < 64; ci++) {
        float2 v = *(const float2*)(g_attn + ci * 16384 + p);
        const float4* wr = (const float4*)(w_s + ci * 64 + co0);
        float4 w0 = wr[0], w1 = wr[1];
        accA[0] = fmaf(w0.x, v.x, accA[0]); accB[0] = fmaf(w0.x, v.y, accB[0]);
        accA[1] = fmaf(w0.y, v.x, accA[1]); accB[1] = fmaf(w0.y, v.y, accB[1]);
        accA[2] = fmaf(w0.z, v.x, accA[2]); accB[2] = fmaf(w0.z, v.y, accB[2]);
        accA[3] = fmaf(w0.w, v.x, accA[3]); accB[3] = fmaf(w0.w, v.y, accB[3]);
        accA[4] = fmaf(w1.x, v.x, accA[4]); accB[4] = fmaf(w1.x, v.y, accB[4]);
        accA[5] = fmaf(w1.y, v.x, accA[5]); accB[5] = fmaf(w1.y, v.y, accB[5]);
        accA[6] = fmaf(w1.z, v.x, accA[6]); accB[6] = fmaf(w1.z, v.y, accB[6]);
        accA[7] = fmaf(w1.w, v.x, accA[7]); accB[7] = fmaf(w1.w, v.y, accB[7]);
    }
    {
        float2 v = *(const float2*)(unet + p);
        const float4* wr = (const float4*)(w_s + 64 * 64 + co0);
        float4 w0 = wr[0], w1 = wr[1];
        accA[0] = fmaf(w0.x, v.x, accA[0]); accB[0] = fmaf(w0.x, v.y, accB[0]);
        accA[1] = fmaf(w0.y, v.x, accA[1]); accB[1] = fmaf(w0.y, v.y, accB[1]);
        accA[2] = fmaf(w0.z, v.x, accA[2]); accB[2] = fmaf(w0.z, v.y, accB[2]);
        accA[3] = fmaf(w0.w, v.x, accA[3]); accB[3] = fmaf(w0.w, v.y, accB[3]);
        accA[4] = fmaf(w1.x, v.x, accA[4]); accB[4] = fmaf(w1.x, v.y, accB[4]);
        accA[5] = fmaf(w1.y, v.x, accA[5]); accB[5] = fmaf(w1.y, v.y, accB[5]);
        accA[6] = fmaf(w1.z, v.x, accA[6]); accB[6] = fmaf(w1.z, v.y, accB[6]);
        accA[7] = fmaf(w1.w, v.x, accA[7]); accB[7] = fmaf(w1.w, v.y, accB[7]);
    }
#pragma unroll
    for (int i = 0; i < 8; i++) {
        int co = co0 + i;
        float2 xv = *(const float2*)(x + co * 16384 + p);
        float bb = bias[co];
        *(float2*)(g_t + co * 16384 + p) = make_float2(xv.x + accA[i] + bb, xv.y + accB[i] + bb);
    }
}

// ---------- 3x3 conv (dil D) via tf32 mma, 64-px tiles; FUSE: + 1x1 conv3 + residual ----------
template <int D, bool FUSE>
__global__ void __launch_bounds__(256) conv_tf32(const float* __restrict__ in,
                                                 const float* __restrict__ wB,
                                                 const float* __restrict__ bias,
                                                 float* __restrict__ out,
                                                 const float* __restrict__ xres,
                                                 const float* __restrict__ b3) {
    constexpr int IH = 8 + 2 * D, IW = 8 + 2 * D, INW = 8 * IH * IW;
    __shared__ float As[64 * 73];
    __shared__ float Bs[64 * 73];
    __shared__ float in_s[INW];
    int t = threadIdx.x, warp = t >> 5, lane = t & 31;
    int g = lane >> 2, tig = lane & 3;
    int mg = warp & 3, ng = warp >> 2;
    int r0 = blockIdx.y * 8, c0 = blockIdx.x * 8;

    float o[4][4];
#pragma unroll
    for (int nb = 0; nb < 4; nb++) {
        float b0 = bias[ng * 32 + nb * 8 + 2 * tig], b1 = bias[ng * 32 + nb * 8 + 2 * tig + 1];
        o[nb][0] = b0; o[nb][1] = b1; o[nb][2] = b0; o[nb][3] = b1;
    }

    int px_b = t >> 2, y_b = px_b >> 3, x_b = px_b & 7;
    int ci0 = (t & 3) * 2;

    for (int grp = 0; grp < 8; grp++) {
        __syncthreads();
        for (int idx = t; idx < INW; idx += 256) {
            int ci = idx / (IH * IW), rem = idx - ci * (IH * IW);
            int rr = rem / IW, cc = rem - rr * IW;
            int gr = r0 - D + rr, gc = c0 - D + cc;
            float v = 0.f;
            if (gr >= 0 && gr < 128 && gc >= 0 && gc < 128)
                v = in[(grp * 8 + ci) * 16384 + gr * 128 + gc];
            in_s[idx] = v;
        }
#pragma unroll
        for (int pass = 0; pass < 18; pass++) {
            int idx = pass * 256 + t;
            int co = idx / 72, k = idx - co * 72;
            Bs[co * 73 + k] = wB[co * 576 + grp * 72 + k];
        }
        __syncthreads();
        {
            const float* ip = in_s + ci0 * (IH * IW) + y_b * IW + x_b;
            float* ap = As + px_b * 73 + ci0 * 9;
#pragma unroll
            for (int cq = 0; cq < 2; cq++)
#pragma unroll
                for (int kh = 0; kh < 3; kh++)
#pragma unroll
                    for (int kw = 0; kw < 3; kw++)
                        ap[cq * 9 + kh * 3 + kw] = __uint_as_float(
                            cvt_tf32(ip[cq * IH * IW + (kh * D) * IW + kw * D]));
        }
        __syncthreads();
        const float* Ar = As + mg * 16 * 73;
#pragma unroll
        for (int kc = 0; kc < 9; kc++) {
            unsigned a0 = __float_as_uint(Ar[g * 73 + kc * 8 + tig]);
            unsigned a1 = __float_as_uint(Ar[(g + 8) * 73 + kc * 8 + tig]);
            unsigned a2 = __float_as_uint(Ar[g * 73 + kc * 8 + tig + 4]);
            unsigned a3 = __float_as_uint(Ar[(g + 8) * 73 + kc * 8 + tig + 4]);
#pragma unroll
            for (int nb = 0; nb < 4; nb++) {
                unsigned b0 = __float_as_uint(Bs[(ng * 32 + nb * 8 + g) * 73 + kc * 8 + tig]);
                unsigned b1 = __float_as_uint(Bs[(ng * 32 + nb * 8 + g) * 73 + kc * 8 + tig + 4]);
                mma_tf32(o[nb], a0, a1, a2, a3, b0, b1);
            }
        }
    }

    // pixel mapping: px = mg*16+g -> (row mg*2, col g); px+8 -> (row mg*2+1, col g)
    int rowA = r0 + mg * 2, colg = c0 + g;
    if (!FUSE) {
#pragma unroll
        for (int nb = 0; nb < 4; nb++) {
            int co = ng * 32 + nb * 8 + 2 * tig;
            out[co * 16384 + rowA * 128 + colg]             = fmaxf(o[nb][0], 0.f);
            out[(co + 1) * 16384 + rowA * 128 + colg]       = fmaxf(o[nb][1], 0.f);
            out[co * 16384 + (rowA + 1) * 128 + colg]       = fmaxf(o[nb][2], 0.f);
            out[(co + 1) * 16384 + (rowA + 1) * 128 + colg] = fmaxf(o[nb][3], 0.f);
        }
    } else {
        __syncthreads();
#pragma unroll
        for (int nb = 0; nb < 4; nb++) {
            int co = ng * 32 + nb * 8 + 2 * tig;
            As[(mg * 16 + g) * 65 + co]         = fmaxf(o[nb][0], 0.f);
            As[(mg * 16 + g) * 65 + co + 1]     = fmaxf(o[nb][1], 0.f);
            As[(mg * 16 + g + 8) * 65 + co]     = fmaxf(o[nb][2], 0.f);
            As[(mg * 16 + g + 8) * 65 + co + 1] = fmaxf(o[nb][3], 0.f);
        }
#pragma unroll
        for (int pass = 0; pass < 16; pass++) {   // W3 tf32 -> Bs pitch 65
            int idx = pass * 256 + t;
            Bs[(idx >> 6) * 65 + (idx & 63)] = g_w3c[idx];
        }
        __syncthreads();
        float o2[4][4];
#pragma unroll
        for (int nb = 0; nb < 4; nb++) {
            float b0 = b3[ng * 32 + nb * 8 + 2 * tig], b1 = b3[ng * 32 + nb * 8 + 2 * tig + 1];
            o2[nb][0] = b0; o2[nb][1] = b1; o2[nb][2] = b0; o2[nb][3] = b1;
        }
        const float* Ar2 = As + mg * 16 * 65;
#pragma unroll
        for (int kc = 0; kc < 8; kc++) {
            unsigned a0 = cvt_tf32(Ar2[g * 65 + kc * 8 + tig]);
            unsigned a1 = cvt_tf32(Ar2[(g + 8) * 65 + kc * 8 + tig]);
            unsigned a2 = cvt_tf32(Ar2[g * 65 + kc * 8 + tig + 4]);
            unsigned a3 = cvt_tf32(Ar2[(g + 8) * 65 + kc * 8 + tig + 4]);
#pragma unroll
            for (int nb = 0; nb < 4; nb++) {
                unsigned b0 = __float_as_uint(Bs[(ng * 32 + nb * 8 + g) * 65 + kc * 8 + tig]);
                unsigned b1 = __float_as_uint(Bs[(ng * 32 + nb * 8 + g) * 65 + kc * 8 + tig + 4]);
                mma_tf32(o2[nb], a0, a1, a2, a3, b0, b1);
            }
        }
#pragma unroll
        for (int nb = 0; nb < 4; nb++) {
            int co = ng * 32 + nb * 8 + 2 * tig;
            out[co * 16384 + rowA * 128 + colg]             = xres[co * 16384 + rowA * 128 + colg]             + o2[nb][0];
            out[(co + 1) * 16384 + rowA * 128 + colg]       = xres[(co + 1) * 16384 + rowA * 128 + colg]       + o2[nb][1];
            out[co * 16384 + (rowA + 1) * 128 + colg]       = xres[co * 16384 + (rowA + 1) * 128 + colg]       + o2[nb][2];
            out[(co + 1) * 16384 + (rowA + 1) * 128 + colg] = xres[(co + 1) * 16384 + (rowA + 1) * 128 + colg] + o2[nb][3];
        }
    }
}

extern "C" void kernel_launch(void* const* d_in, const int* in_sizes, int n_in,
                              void* d_out, int out_size) {
    const float* x     = (const float*)d_in[0];
    const float* unet  = (const float*)d_in[1];
    const float* wqk   = (const float*)d_in[2];
    const float* c1w   = (const float*)d_in[3];
    const float* c1b   = (const float*)d_in[4];
    const float* c2w   = (const float*)d_in[5];
    const float* c2b   = (const float*)d_in[6];
    const float* c3w   = (const float*)d_in[7];
    const float* c3b   = (const float*)d_in[8];
    const float* clw   = (const float*)d_in[9];
    const float* clb   = (const float*)d_in[10];
    float* out = (float*)d_out;

    cudaFuncSetAttribute(attn_mma, cudaFuncAttributeMaxDynamicSharedMemorySize, 2 * BUFB);

    prep_all<<<144, 256>>>(x, c1w, c2w, c3w, clw, wqk);
    qv_build<<<1024, 256>>>(x, wqk);
    attn_mma<<<dim3(64, 4), 128, 2 * BUFB>>>();
    convl_fused<<<256, 256>>>(unet, x, clb);
    float* z1;  cudaGetSymbolAddress((void**)&z1, g_z1);
    float* tt;  cudaGetSymbolAddress((void**)&tt, g_t);
    float* wc1; cudaGetSymbolAddress((void**)&wc1, g_wc1);
    float* wc2; cudaGetSymbolAddress((void**)&wc2, g_wc2);
    conv_tf32<1, false><<<dim3(16, 16), 256>>>(tt, wc1, c1b, z1, nullptr, nullptr);
    conv_tf32<2, true><<<dim3(16, 16), 256>>>(z1, wc2, c2b, out, x, c3b);
}